// round 2
// baseline (speedup 1.0000x reference)
#include <cuda_runtime.h>
#include <math.h>

#define N 8192
#define D 1024
#define C 1000

// Scratch (device globals: no allocation allowed)
static __device__ float g_featn[(size_t)N * D];   // normalized features
static __device__ float g_sumexp[N];              // per-row sum_{j!=i} exp(sim)
static __device__ float g_possum[N];              // per-row sum over positives of sim
static __device__ float g_ce[N];                  // per-row CE
static __device__ int   g_hist[C];                // label histogram

// ---------------------------------------------------------------------------
__global__ void k_init() {
    int i = blockIdx.x * blockDim.x + threadIdx.x;
    if (i < N) { g_sumexp[i] = 0.f; g_possum[i] = 0.f; }
    if (i < C) g_hist[i] = 0;
}

// ---------------------------------------------------------------------------
// Row L2 normalization + label histogram
__global__ __launch_bounds__(256) void k_norm_hist(const float* __restrict__ feat,
                                                   const int* __restrict__ labels) {
    int row = blockIdx.x;
    int tid = threadIdx.x;
    const float* f = feat + (size_t)row * D;
    float s = 0.f;
    for (int j = tid; j < D; j += 256) { float v = f[j]; s += v * v; }
    __shared__ float red[8];
    for (int o = 16; o > 0; o >>= 1) s += __shfl_xor_sync(0xffffffffu, s, o);
    if ((tid & 31) == 0) red[tid >> 5] = s;
    __syncthreads();
    __shared__ float bc;
    if (tid == 0) {
        float v = 0.f;
        #pragma unroll
        for (int w = 0; w < 8; w++) v += red[w];
        bc = rsqrtf(v);
        atomicAdd(&g_hist[labels[row]], 1);
    }
    __syncthreads();
    float inv = bc;
    float* out = g_featn + (size_t)row * D;
    for (int j = tid; j < D; j += 256) out[j] = f[j] * inv;
}

// ---------------------------------------------------------------------------
// Logits GEMM: out[N,C] = feat @ W^T + b   (both operands K-contiguous)
__global__ __launch_bounds__(256) void k_logits(const float* __restrict__ A,
                                                const float* __restrict__ W,
                                                const float* __restrict__ bias,
                                                float* __restrict__ out) {
    __shared__ float As[16][128];
    __shared__ float Bs[16][128];
    int tid = threadIdx.x;
    int rowBase = blockIdx.y * 128;
    int colBase = blockIdx.x * 128;
    int lr = tid >> 1;            // 0..127
    int lc = (tid & 1) << 3;      // 0 or 8
    int tx = tid & 15, ty = tid >> 4;

    const float* Ap = A + (size_t)(rowBase + lr) * D + lc;
    int wrow = colBase + lr;
    bool bv = wrow < C;
    const float* Bp = W + (size_t)(bv ? wrow : 0) * D + lc;

    float c[8][8];
    #pragma unroll
    for (int i = 0; i < 8; i++)
        #pragma unroll
        for (int j = 0; j < 8; j++) c[i][j] = 0.f;

    for (int k0 = 0; k0 < D; k0 += 16) {
        float4 a0 = *(const float4*)(Ap + k0);
        float4 a1 = *(const float4*)(Ap + k0 + 4);
        float4 b0 = make_float4(0.f, 0.f, 0.f, 0.f);
        float4 b1 = make_float4(0.f, 0.f, 0.f, 0.f);
        if (bv) { b0 = *(const float4*)(Bp + k0); b1 = *(const float4*)(Bp + k0 + 4); }
        __syncthreads();
        As[lc + 0][lr] = a0.x; As[lc + 1][lr] = a0.y; As[lc + 2][lr] = a0.z; As[lc + 3][lr] = a0.w;
        As[lc + 4][lr] = a1.x; As[lc + 5][lr] = a1.y; As[lc + 6][lr] = a1.z; As[lc + 7][lr] = a1.w;
        Bs[lc + 0][lr] = b0.x; Bs[lc + 1][lr] = b0.y; Bs[lc + 2][lr] = b0.z; Bs[lc + 3][lr] = b0.w;
        Bs[lc + 4][lr] = b1.x; Bs[lc + 5][lr] = b1.y; Bs[lc + 6][lr] = b1.z; Bs[lc + 7][lr] = b1.w;
        __syncthreads();
        #pragma unroll
        for (int k = 0; k < 16; k++) {
            float4 a_0 = *(const float4*)&As[k][ty * 8];
            float4 a_1 = *(const float4*)&As[k][ty * 8 + 4];
            float4 b_0 = *(const float4*)&Bs[k][tx * 8];
            float4 b_1 = *(const float4*)&Bs[k][tx * 8 + 4];
            float ar[8] = {a_0.x, a_0.y, a_0.z, a_0.w, a_1.x, a_1.y, a_1.z, a_1.w};
            float br[8] = {b_0.x, b_0.y, b_0.z, b_0.w, b_1.x, b_1.y, b_1.z, b_1.w};
            #pragma unroll
            for (int i = 0; i < 8; i++)
                #pragma unroll
                for (int j = 0; j < 8; j++)
                    c[i][j] = fmaf(ar[i], br[j], c[i][j]);
        }
    }

    #pragma unroll
    for (int i = 0; i < 8; i++) {
        int gr = rowBase + ty * 8 + i;
        #pragma unroll
        for (int j = 0; j < 8; j++) {
            int gc = colBase + tx * 8 + j;
            if (gc < C) out[(size_t)gr * C + gc] = c[i][j] + __ldg(&bias[gc]);
        }
    }
}

// ---------------------------------------------------------------------------
// CE per row: stable log-softmax + pick label
__global__ __launch_bounds__(256) void k_ce(const float* __restrict__ logits,
                                            const int* __restrict__ labels) {
    int row = blockIdx.x;
    int tid = threadIdx.x;
    const float* x = logits + (size_t)row * C;
    float m = -1e30f;
    for (int j = tid; j < C; j += 256) m = fmaxf(m, x[j]);
    __shared__ float red[8];
    __shared__ float bc;
    for (int o = 16; o > 0; o >>= 1) m = fmaxf(m, __shfl_xor_sync(0xffffffffu, m, o));
    if ((tid & 31) == 0) red[tid >> 5] = m;
    __syncthreads();
    if (tid == 0) {
        float v = red[0];
        #pragma unroll
        for (int w = 1; w < 8; w++) v = fmaxf(v, red[w]);
        bc = v;
    }
    __syncthreads();
    m = bc;
    float s = 0.f;
    for (int j = tid; j < C; j += 256) s += expf(x[j] - m);
    for (int o = 16; o > 0; o >>= 1) s += __shfl_xor_sync(0xffffffffu, s, o);
    if ((tid & 31) == 0) red[tid >> 5] = s;
    __syncthreads();
    if (tid == 0) {
        float v = 0.f;
        #pragma unroll
        for (int w = 0; w < 8; w++) v += red[w];
        int lab = labels[row];
        g_ce[row] = -(x[lab] - m - logf(v));
    }
}

// ---------------------------------------------------------------------------
// SCL: blocked A@A^T with fused row-reduction epilogue.
// sim in [-1/0.3, 1/0.3] so exp never overflows -> no online max needed.
__global__ __launch_bounds__(256) void k_scl(const int* __restrict__ labels) {
    __shared__ float As[16][128];
    __shared__ float Bs[16][128];
    __shared__ int rowLab[128], colLab[128];
    int tid = threadIdx.x;
    int rowBase = blockIdx.y * 128;
    int colBase = blockIdx.x * 128;
    if (tid < 128) rowLab[tid] = labels[rowBase + tid];
    else           colLab[tid - 128] = labels[colBase + tid - 128];

    int lr = tid >> 1;
    int lc = (tid & 1) << 3;
    int tx = tid & 15, ty = tid >> 4;
    const float* Ap = g_featn + (size_t)(rowBase + lr) * D + lc;
    const float* Bp = g_featn + (size_t)(colBase + lr) * D + lc;

    float c[8][8];
    #pragma unroll
    for (int i = 0; i < 8; i++)
        #pragma unroll
        for (int j = 0; j < 8; j++) c[i][j] = 0.f;

    for (int k0 = 0; k0 < D; k0 += 16) {
        float4 a0 = *(const float4*)(Ap + k0);
        float4 a1 = *(const float4*)(Ap + k0 + 4);
        float4 b0 = *(const float4*)(Bp + k0);
        float4 b1 = *(const float4*)(Bp + k0 + 4);
        __syncthreads();
        As[lc + 0][lr] = a0.x; As[lc + 1][lr] = a0.y; As[lc + 2][lr] = a0.z; As[lc + 3][lr] = a0.w;
        As[lc + 4][lr] = a1.x; As[lc + 5][lr] = a1.y; As[lc + 6][lr] = a1.z; As[lc + 7][lr] = a1.w;
        Bs[lc + 0][lr] = b0.x; Bs[lc + 1][lr] = b0.y; Bs[lc + 2][lr] = b0.z; Bs[lc + 3][lr] = b0.w;
        Bs[lc + 4][lr] = b1.x; Bs[lc + 5][lr] = b1.y; Bs[lc + 6][lr] = b1.z; Bs[lc + 7][lr] = b1.w;
        __syncthreads();
        #pragma unroll
        for (int k = 0; k < 16; k++) {
            float4 a_0 = *(const float4*)&As[k][ty * 8];
            float4 a_1 = *(const float4*)&As[k][ty * 8 + 4];
            float4 b_0 = *(const float4*)&Bs[k][tx * 8];
            float4 b_1 = *(const float4*)&Bs[k][tx * 8 + 4];
            float ar[8] = {a_0.x, a_0.y, a_0.z, a_0.w, a_1.x, a_1.y, a_1.z, a_1.w};
            float br[8] = {b_0.x, b_0.y, b_0.z, b_0.w, b_1.x, b_1.y, b_1.z, b_1.w};
            #pragma unroll
            for (int i = 0; i < 8; i++)
                #pragma unroll
                for (int j = 0; j < 8; j++)
                    c[i][j] = fmaf(ar[i], br[j], c[i][j]);
        }
    }

    const float invt = 1.0f / 0.3f;
    #pragma unroll
    for (int i = 0; i < 8; i++) {
        int lrow = ty * 8 + i;
        int gr = rowBase + lrow;
        int rl = rowLab[lrow];
        float se = 0.f, ps = 0.f;
        #pragma unroll
        for (int j = 0; j < 8; j++) {
            int lcol = tx * 8 + j;
            int gc = colBase + lcol;
            float sim = c[i][j] * invt;
            if (gc != gr) {
                se += expf(sim);
                if (colLab[lcol] == rl) ps += sim;
            }
        }
        // reduce across the 16 lanes that share this row (lanes 0-15 / 16-31)
        #pragma unroll
        for (int o = 8; o > 0; o >>= 1) {
            se += __shfl_down_sync(0xffffffffu, se, o);
            ps += __shfl_down_sync(0xffffffffu, ps, o);
        }
        if ((tid & 15) == 0) {
            atomicAdd(&g_sumexp[gr], se);
            atomicAdd(&g_possum[gr], ps);
        }
    }
}

// ---------------------------------------------------------------------------
__global__ __launch_bounds__(256) void k_final(const int* __restrict__ labels,
                                               float* __restrict__ out_loss) {
    int tid = threadIdx.x;
    float ce = 0.f, scl = 0.f;
    int nv = 0;
    for (int i = tid; i < N; i += 256) {
        ce += g_ce[i];
        int cnt = g_hist[labels[i]] - 1;
        if (cnt > 0) {
            float lse = logf(g_sumexp[i]);
            scl += lse - g_possum[i] / (float)cnt;
            nv++;
        }
    }
    __shared__ float sc[256], ss[256];
    __shared__ int sn[256];
    sc[tid] = ce; ss[tid] = scl; sn[tid] = nv;
    __syncthreads();
    for (int o = 128; o > 0; o >>= 1) {
        if (tid < o) { sc[tid] += sc[tid + o]; ss[tid] += ss[tid + o]; sn[tid] += sn[tid + o]; }
        __syncthreads();
    }
    if (tid == 0) {
        float cem = sc[0] / (float)N;
        float sclm = (sn[0] > 0) ? (ss[0] / (float)sn[0]) : 0.f;
        *out_loss = 0.9f * cem + 0.1f * sclm;
    }
}

// ---------------------------------------------------------------------------
extern "C" void kernel_launch(void* const* d_in, const int* in_sizes, int n_in,
                              void* d_out, int out_size) {
    const float* feat   = (const float*)d_in[0];
    const int*   labels = (const int*)d_in[1];
    const float* W      = (const float*)d_in[2];
    const float* b      = (const float*)d_in[3];
    float* out = (float*)d_out;

    k_init<<<(N + 255) / 256, 256>>>();
    k_norm_hist<<<N, 256>>>(feat, labels);
    k_logits<<<dim3((C + 127) / 128, N / 128), 256>>>(feat, W, b, out);
    k_ce<<<N, 256>>>(out, labels);
    k_scl<<<dim3(N / 128, N / 128), 256>>>(labels);
    k_final<<<1, 256>>>(labels, out + (size_t)out_size - 1);
}

// round 5
// speedup vs baseline: 3.7717x; 3.7717x over previous
#include <cuda_runtime.h>
#include <cuda_bf16.h>
#include <math.h>
#include <stdint.h>

#define N 8192
#define D 1024
#define C 1000

// ---------------------------------------------------------------------------
// Device scratch (no allocations allowed)
static __device__ __nv_bfloat16 g_featb[(size_t)N * D];  // normalized feats, bf16
static __device__ float g_sumexp[N];
static __device__ float g_possum[N];
static __device__ float g_ce[N];
static __device__ int   g_hist[C];

// ---------------------------------------------------------------------------
__device__ __forceinline__ uint32_t smem_u32(const void* p) {
    uint32_t a;
    asm("{ .reg .u64 t; cvta.to.shared.u64 t, %1; cvt.u32.u64 %0, t; }" : "=r"(a) : "l"(p));
    return a;
}

__device__ __forceinline__ void cp16(uint32_t saddr, const void* g) {
    asm volatile("cp.async.ca.shared.global [%0], [%1], 16;" :: "r"(saddr), "l"(g));
}
#define CP_COMMIT() asm volatile("cp.async.commit_group;" ::: "memory")
#define CP_WAIT1()  asm volatile("cp.async.wait_group 1;" ::: "memory")
#define CP_WAIT0()  asm volatile("cp.async.wait_group 0;" ::: "memory")

__device__ __forceinline__ void ldm_x4(uint32_t* d, uint32_t addr) {
    asm volatile("ldmatrix.sync.aligned.m8n8.x4.shared.b16 {%0,%1,%2,%3}, [%4];"
        : "=r"(d[0]), "=r"(d[1]), "=r"(d[2]), "=r"(d[3]) : "r"(addr));
}

__device__ __forceinline__ void mma_bf16(float* c, const uint32_t* a, uint32_t b0, uint32_t b1) {
    asm volatile("mma.sync.aligned.m16n8k16.row.col.f32.bf16.bf16.f32 "
        "{%0,%1,%2,%3}, {%4,%5,%6,%7}, {%8,%9}, {%0,%1,%2,%3};"
        : "+f"(c[0]), "+f"(c[1]), "+f"(c[2]), "+f"(c[3])
        : "r"(a[0]), "r"(a[1]), "r"(a[2]), "r"(a[3]), "r"(b0), "r"(b1));
}

// SW128 swizzle on a 128-byte-row tile
#define SWZ(o) ((o) ^ (((o) >> 3) & 0x70))

// ---------------------------------------------------------------------------
__global__ void k_init() {
    int i = blockIdx.x * blockDim.x + threadIdx.x;
    if (i < N) { g_sumexp[i] = 0.f; g_possum[i] = 0.f; }
    if (i < C) g_hist[i] = 0;
}

// ---------------------------------------------------------------------------
// Row L2 norm -> bf16, plus label histogram
__global__ __launch_bounds__(256) void k_norm_hist(const float* __restrict__ feat,
                                                   const int* __restrict__ labels) {
    int row = blockIdx.x;
    int tid = threadIdx.x;
    const float* f = feat + (size_t)row * D;
    float s = 0.f;
    for (int j = tid; j < D; j += 256) { float v = f[j]; s += v * v; }
    __shared__ float red[8];
    for (int o = 16; o > 0; o >>= 1) s += __shfl_xor_sync(0xffffffffu, s, o);
    if ((tid & 31) == 0) red[tid >> 5] = s;
    __syncthreads();
    __shared__ float bc;
    if (tid == 0) {
        float v = 0.f;
        #pragma unroll
        for (int w = 0; w < 8; w++) v += red[w];
        bc = rsqrtf(v);
        atomicAdd(&g_hist[labels[row]], 1);
    }
    __syncthreads();
    float inv = bc;
    __nv_bfloat16* out = g_featb + (size_t)row * D;
    for (int j = tid; j < D; j += 256) out[j] = __float2bfloat16(f[j] * inv);
}

// ---------------------------------------------------------------------------
// Logits GEMM: out[N,C] = feat @ W^T + b  (fp32 — exact output matters)
__global__ __launch_bounds__(256) void k_logits(const float* __restrict__ A,
                                                const float* __restrict__ W,
                                                const float* __restrict__ bias,
                                                float* __restrict__ out) {
    __shared__ float As[16][128];
    __shared__ float Bs[16][128];
    int tid = threadIdx.x;
    int rowBase = blockIdx.y * 128;
    int colBase = blockIdx.x * 128;
    int lr = tid >> 1;
    int lc = (tid & 1) << 3;
    int tx = tid & 15, ty = tid >> 4;

    const float* Ap = A + (size_t)(rowBase + lr) * D + lc;
    int wrow = colBase + lr;
    bool bv = wrow < C;
    const float* Bp = W + (size_t)(bv ? wrow : 0) * D + lc;

    float c[8][8];
    #pragma unroll
    for (int i = 0; i < 8; i++)
        #pragma unroll
        for (int j = 0; j < 8; j++) c[i][j] = 0.f;

    for (int k0 = 0; k0 < D; k0 += 16) {
        float4 a0 = *(const float4*)(Ap + k0);
        float4 a1 = *(const float4*)(Ap + k0 + 4);
        float4 b0 = make_float4(0.f, 0.f, 0.f, 0.f);
        float4 b1 = make_float4(0.f, 0.f, 0.f, 0.f);
        if (bv) { b0 = *(const float4*)(Bp + k0); b1 = *(const float4*)(Bp + k0 + 4); }
        __syncthreads();
        As[lc + 0][lr] = a0.x; As[lc + 1][lr] = a0.y; As[lc + 2][lr] = a0.z; As[lc + 3][lr] = a0.w;
        As[lc + 4][lr] = a1.x; As[lc + 5][lr] = a1.y; As[lc + 6][lr] = a1.z; As[lc + 7][lr] = a1.w;
        Bs[lc + 0][lr] = b0.x; Bs[lc + 1][lr] = b0.y; Bs[lc + 2][lr] = b0.z; Bs[lc + 3][lr] = b0.w;
        Bs[lc + 4][lr] = b1.x; Bs[lc + 5][lr] = b1.y; Bs[lc + 6][lr] = b1.z; Bs[lc + 7][lr] = b1.w;
        __syncthreads();
        #pragma unroll
        for (int k = 0; k < 16; k++) {
            float4 a_0 = *(const float4*)&As[k][ty * 8];
            float4 a_1 = *(const float4*)&As[k][ty * 8 + 4];
            float4 b_0 = *(const float4*)&Bs[k][tx * 8];
            float4 b_1 = *(const float4*)&Bs[k][tx * 8 + 4];
            float ar[8] = {a_0.x, a_0.y, a_0.z, a_0.w, a_1.x, a_1.y, a_1.z, a_1.w};
            float br[8] = {b_0.x, b_0.y, b_0.z, b_0.w, b_1.x, b_1.y, b_1.z, b_1.w};
            #pragma unroll
            for (int i = 0; i < 8; i++)
                #pragma unroll
                for (int j = 0; j < 8; j++)
                    c[i][j] = fmaf(ar[i], br[j], c[i][j]);
        }
    }

    #pragma unroll
    for (int i = 0; i < 8; i++) {
        int gr = rowBase + ty * 8 + i;
        #pragma unroll
        for (int j = 0; j < 8; j++) {
            int gc = colBase + tx * 8 + j;
            if (gc < C) out[(size_t)gr * C + gc] = c[i][j] + __ldg(&bias[gc]);
        }
    }
}

// ---------------------------------------------------------------------------
// CE per row
__global__ __launch_bounds__(256) void k_ce(const float* __restrict__ logits,
                                            const int* __restrict__ labels) {
    int row = blockIdx.x;
    int tid = threadIdx.x;
    const float* x = logits + (size_t)row * C;
    float m = -1e30f;
    for (int j = tid; j < C; j += 256) m = fmaxf(m, x[j]);
    __shared__ float red[8];
    __shared__ float bc;
    for (int o = 16; o > 0; o >>= 1) m = fmaxf(m, __shfl_xor_sync(0xffffffffu, m, o));
    if ((tid & 31) == 0) red[tid >> 5] = m;
    __syncthreads();
    if (tid == 0) {
        float v = red[0];
        #pragma unroll
        for (int w = 1; w < 8; w++) v = fmaxf(v, red[w]);
        bc = v;
    }
    __syncthreads();
    m = bc;
    float s = 0.f;
    for (int j = tid; j < C; j += 256) s += expf(x[j] - m);
    for (int o = 16; o > 0; o >>= 1) s += __shfl_xor_sync(0xffffffffu, s, o);
    if ((tid & 31) == 0) red[tid >> 5] = s;
    __syncthreads();
    if (tid == 0) {
        float v = 0.f;
        #pragma unroll
        for (int w = 0; w < 8; w++) v += red[w];
        int lab = labels[row];
        g_ce[row] = -(x[lab] - m - logf(v));
    }
}

// ---------------------------------------------------------------------------
// SCL sim GEMM via mma.sync bf16 (HMMA): 128x128 CTA tile, 8 warps of 32x64,
// K chunked by 64, cp.async double buffer, fused exp/possum epilogue.
//
// SMEM: [0,512) rowLab, [512,1024) colLab, [1024 + s*32768) stage s: A(16KB)+B(16KB)
#define SCL_SMEM (1024 + 2 * 32768)
#define NKC 16   // K chunks of 64

__global__ __launch_bounds__(256) void k_scl_mma(const int* __restrict__ labels) {
    extern __shared__ char smem[];
    const uint32_t sb = smem_u32(smem);
    const int tid = threadIdx.x;
    const int lane = tid & 31;
    const int wid = tid >> 5;
    const int rowBase = blockIdx.y * 128;
    const int colBase = blockIdx.x * 128;

    int* rowLab = (int*)smem;
    int* colLab = (int*)(smem + 512);
    if (tid < 128) rowLab[tid] = labels[rowBase + tid];
    else           colLab[tid - 128] = labels[colBase + tid - 128];

    // ---- global load addressing (per thread: 4 rows x 16B of A and B) ----
    const int ldr = tid >> 3;            // 0..31, +32 per rr
    const int ldc = (tid & 7) * 16;      // byte within 128B row chunk
    const char* gb = (const char*)g_featb;

    // ---- warp tiling ----
    const int mr = (wid >> 1) * 32;      // warp row base in tile
    const int nc = (wid & 1) * 64;       // warp col base in tile

    float acc[2][8][4];
    #pragma unroll
    for (int i = 0; i < 2; i++)
        #pragma unroll
        for (int j = 0; j < 8; j++)
            #pragma unroll
            for (int u = 0; u < 4; u++) acc[i][j][u] = 0.f;

    // ---- pipeline ----
    // stage s buffers
    uint32_t sA[2], sB[2];
    #pragma unroll
    for (int s = 0; s < 2; s++) { sA[s] = sb + 1024 + s * 32768; sB[s] = sA[s] + 16384; }

    // prologue: load chunk 0
    {
        #pragma unroll
        for (int rr = 0; rr < 4; rr++) {
            int r = ldr + rr * 32;
            uint32_t sw = SWZ((uint32_t)(r * 128 + ldc));
            cp16(sA[0] + sw, gb + (size_t)(rowBase + r) * 2048 + ldc);
            cp16(sB[0] + sw, gb + (size_t)(colBase + r) * 2048 + ldc);
        }
        CP_COMMIT();
    }

    for (int kc = 0; kc < NKC; kc++) {
        if (kc + 1 < NKC) {
            const int s = (kc + 1) & 1;
            const size_t go = (size_t)(kc + 1) * 128 + ldc;
            #pragma unroll
            for (int rr = 0; rr < 4; rr++) {
                int r = ldr + rr * 32;
                uint32_t sw = SWZ((uint32_t)(r * 128 + ldc));
                cp16(sA[s] + sw, gb + (size_t)(rowBase + r) * 2048 + go);
                cp16(sB[s] + sw, gb + (size_t)(colBase + r) * 2048 + go);
            }
            CP_COMMIT();
            CP_WAIT1();
        } else {
            CP_WAIT0();
        }
        __syncthreads();

        const uint32_t bufA = sA[kc & 1];
        const uint32_t bufB = sB[kc & 1];
        const int klane = (lane >> 4) << 4;   // 0 or 16 byte offset (k-half)
        #pragma unroll
        for (int ks = 0; ks < 4; ks++) {
            const int kb = ks * 32 + klane;
            uint32_t af[2][4];
            #pragma unroll
            for (int i = 0; i < 2; i++) {
                int r = mr + i * 16 + (lane & 15);
                ldm_x4(af[i], bufA + SWZ((uint32_t)(r * 128 + kb)));
            }
            #pragma unroll
            for (int j = 0; j < 4; j++) {
                uint32_t bf[4];
                int nr = nc + j * 16 + (lane & 15);
                ldm_x4(bf, bufB + SWZ((uint32_t)(nr * 128 + kb)));
                #pragma unroll
                for (int i = 0; i < 2; i++) {
                    mma_bf16(acc[i][j * 2 + 0], af[i], bf[0], bf[1]);
                    mma_bf16(acc[i][j * 2 + 1], af[i], bf[2], bf[3]);
                }
            }
        }
        __syncthreads();
    }

    // ---- fused epilogue ----
    const int g = lane >> 2, t = lane & 3;
    const float invt = 1.0f / 0.3f;
    #pragma unroll
    for (int i = 0; i < 2; i++) {
        const int r0 = mr + i * 16 + g;
        const int r1 = r0 + 8;
        const int gr0 = rowBase + r0, gr1 = rowBase + r1;
        const int rl0 = rowLab[r0], rl1 = rowLab[r1];
        float se0 = 0.f, ps0 = 0.f, se1 = 0.f, ps1 = 0.f;
        #pragma unroll
        for (int j = 0; j < 8; j++) {
            #pragma unroll
            for (int u = 0; u < 2; u++) {
                const int col = nc + j * 8 + t * 2 + u;
                const int gc = colBase + col;
                const int cl = colLab[col];
                const float s0 = acc[i][j][u] * invt;
                const float s1 = acc[i][j][2 + u] * invt;
                if (gc != gr0) { se0 += __expf(s0); if (cl == rl0) ps0 += s0; }
                if (gc != gr1) { se1 += __expf(s1); if (cl == rl1) ps1 += s1; }
            }
        }
        #pragma unroll
        for (int o = 1; o <= 2; o <<= 1) {
            se0 += __shfl_xor_sync(0xffffffffu, se0, o);
            ps0 += __shfl_xor_sync(0xffffffffu, ps0, o);
            se1 += __shfl_xor_sync(0xffffffffu, se1, o);
            ps1 += __shfl_xor_sync(0xffffffffu, ps1, o);
        }
        if (t == 0) {
            atomicAdd(&g_sumexp[gr0], se0);
            atomicAdd(&g_possum[gr0], ps0);
            atomicAdd(&g_sumexp[gr1], se1);
            atomicAdd(&g_possum[gr1], ps1);
        }
    }
}

// ---------------------------------------------------------------------------
__global__ __launch_bounds__(256) void k_final(const int* __restrict__ labels,
                                               float* __restrict__ out_loss) {
    int tid = threadIdx.x;
    float ce = 0.f, scl = 0.f;
    int nv = 0;
    for (int i = tid; i < N; i += 256) {
        ce += g_ce[i];
        int cnt = g_hist[labels[i]] - 1;
        if (cnt > 0) {
            float lse = logf(g_sumexp[i]);
            scl += lse - g_possum[i] / (float)cnt;
            nv++;
        }
    }
    __shared__ float sc[256], ss[256];
    __shared__ int sn[256];
    sc[tid] = ce; ss[tid] = scl; sn[tid] = nv;
    __syncthreads();
    for (int o = 128; o > 0; o >>= 1) {
        if (tid < o) { sc[tid] += sc[tid + o]; ss[tid] += ss[tid + o]; sn[tid] += sn[tid + o]; }
        __syncthreads();
    }
    if (tid == 0) {
        float cem = sc[0] / (float)N;
        float sclm = (sn[0] > 0) ? (ss[0] / (float)sn[0]) : 0.f;
        *out_loss = 0.9f * cem + 0.1f * sclm;
    }
}

// ---------------------------------------------------------------------------
extern "C" void kernel_launch(void* const* d_in, const int* in_sizes, int n_in,
                              void* d_out, int out_size) {
    const float* feat   = (const float*)d_in[0];
    const int*   labels = (const int*)d_in[1];
    const float* W      = (const float*)d_in[2];
    const float* b      = (const float*)d_in[3];
    float* out = (float*)d_out;

    static int smem_set = 0;
    if (!smem_set) {
        cudaFuncSetAttribute(k_scl_mma, cudaFuncAttributeMaxDynamicSharedMemorySize, SCL_SMEM);
        smem_set = 1;
    }

    k_init<<<(N + 255) / 256, 256>>>();
    k_norm_hist<<<N, 256>>>(feat, labels);
    k_logits<<<dim3((C + 127) / 128, N / 128), 256>>>(feat, W, b, out);
    k_ce<<<N, 256>>>(out, labels);
    k_scl_mma<<<dim3(N / 128, N / 128), 256, SCL_SMEM>>>(labels);
    k_final<<<1, 256>>>(labels, out + (size_t)out_size - 1);
}

// round 12
// speedup vs baseline: 4.6910x; 1.2437x over previous
#include <cuda_runtime.h>
#include <cuda_bf16.h>
#include <math.h>
#include <stdint.h>

#define N 8192
#define D 1024
#define C 1000

// ---------------------------------------------------------------------------
// Device scratch (no allocations allowed)
static __device__ __nv_bfloat16 g_featb[(size_t)N * D];  // normalized feats, bf16
static __device__ float g_sumexp[N];
static __device__ float g_possum[N];
static __device__ float g_ce[N];
static __device__ int   g_hist[C];

// ---------------------------------------------------------------------------
__device__ __forceinline__ uint32_t smem_u32(const void* p) {
    uint32_t a;
    asm("{ .reg .u64 t; cvta.to.shared.u64 t, %1; cvt.u32.u64 %0, t; }" : "=r"(a) : "l"(p));
    return a;
}

__device__ __forceinline__ void cp16(uint32_t saddr, const void* g) {
    asm volatile("cp.async.ca.shared.global [%0], [%1], 16;" :: "r"(saddr), "l"(g));
}
#define CP_COMMIT() asm volatile("cp.async.commit_group;" ::: "memory")
#define CP_WAIT1()  asm volatile("cp.async.wait_group 1;" ::: "memory")
#define CP_WAIT0()  asm volatile("cp.async.wait_group 0;" ::: "memory")

__device__ __forceinline__ void ldm_x4(uint32_t* d, uint32_t addr) {
    asm volatile("ldmatrix.sync.aligned.m8n8.x4.shared.b16 {%0,%1,%2,%3}, [%4];"
        : "=r"(d[0]), "=r"(d[1]), "=r"(d[2]), "=r"(d[3]) : "r"(addr));
}

__device__ __forceinline__ void mma_bf16(float* c, const uint32_t* a, uint32_t b0, uint32_t b1) {
    asm volatile("mma.sync.aligned.m16n8k16.row.col.f32.bf16.bf16.f32 "
        "{%0,%1,%2,%3}, {%4,%5,%6,%7}, {%8,%9}, {%0,%1,%2,%3};"
        : "+f"(c[0]), "+f"(c[1]), "+f"(c[2]), "+f"(c[3])
        : "r"(a[0]), "r"(a[1]), "r"(a[2]), "r"(a[3]), "r"(b0), "r"(b1));
}

// SW128 swizzle on a 128-byte-row tile
#define SWZ(o) ((o) ^ (((o) >> 3) & 0x70))

// ---------------------------------------------------------------------------
__global__ void k_init() {
    int i = blockIdx.x * blockDim.x + threadIdx.x;
    if (i < N) { g_sumexp[i] = 0.f; g_possum[i] = 0.f; }
    if (i < C) g_hist[i] = 0;
}

// ---------------------------------------------------------------------------
// Row L2 norm -> bf16, plus label histogram  (identical to R5 passing version)
__global__ __launch_bounds__(256) void k_norm_hist(const float* __restrict__ feat,
                                                   const int* __restrict__ labels) {
    int row = blockIdx.x;
    int tid = threadIdx.x;
    const float* f = feat + (size_t)row * D;
    float s = 0.f;
    for (int j = tid; j < D; j += 256) { float v = f[j]; s += v * v; }
    __shared__ float red[8];
    for (int o = 16; o > 0; o >>= 1) s += __shfl_xor_sync(0xffffffffu, s, o);
    if ((tid & 31) == 0) red[tid >> 5] = s;
    __syncthreads();
    __shared__ float bc;
    if (tid == 0) {
        float v = 0.f;
        #pragma unroll
        for (int w = 0; w < 8; w++) v += red[w];
        bc = rsqrtf(v);
        atomicAdd(&g_hist[labels[row]], 1);
    }
    __syncthreads();
    float inv = bc;
    __nv_bfloat16* out = g_featb + (size_t)row * D;
    for (int j = tid; j < D; j += 256) out[j] = __float2bfloat16(f[j] * inv);
}

// ---------------------------------------------------------------------------
// Logits GEMM: out[N,C] = feat @ W^T + b  (fp32 — identical to R5 passing version)
__global__ __launch_bounds__(256) void k_logits(const float* __restrict__ A,
                                                const float* __restrict__ W,
                                                const float* __restrict__ bias,
                                                float* __restrict__ out) {
    __shared__ float As[16][128];
    __shared__ float Bs[16][128];
    int tid = threadIdx.x;
    int rowBase = blockIdx.y * 128;
    int colBase = blockIdx.x * 128;
    int lr = tid >> 1;
    int lc = (tid & 1) << 3;
    int tx = tid & 15, ty = tid >> 4;

    const float* Ap = A + (size_t)(rowBase + lr) * D + lc;
    int wrow = colBase + lr;
    bool bv = wrow < C;
    const float* Bp = W + (size_t)(bv ? wrow : 0) * D + lc;

    float c[8][8];
    #pragma unroll
    for (int i = 0; i < 8; i++)
        #pragma unroll
        for (int j = 0; j < 8; j++) c[i][j] = 0.f;

    for (int k0 = 0; k0 < D; k0 += 16) {
        float4 a0 = *(const float4*)(Ap + k0);
        float4 a1 = *(const float4*)(Ap + k0 + 4);
        float4 b0 = make_float4(0.f, 0.f, 0.f, 0.f);
        float4 b1 = make_float4(0.f, 0.f, 0.f, 0.f);
        if (bv) { b0 = *(const float4*)(Bp + k0); b1 = *(const float4*)(Bp + k0 + 4); }
        __syncthreads();
        As[lc + 0][lr] = a0.x; As[lc + 1][lr] = a0.y; As[lc + 2][lr] = a0.z; As[lc + 3][lr] = a0.w;
        As[lc + 4][lr] = a1.x; As[lc + 5][lr] = a1.y; As[lc + 6][lr] = a1.z; As[lc + 7][lr] = a1.w;
        Bs[lc + 0][lr] = b0.x; Bs[lc + 1][lr] = b0.y; Bs[lc + 2][lr] = b0.z; Bs[lc + 3][lr] = b0.w;
        Bs[lc + 4][lr] = b1.x; Bs[lc + 5][lr] = b1.y; Bs[lc + 6][lr] = b1.z; Bs[lc + 7][lr] = b1.w;
        __syncthreads();
        #pragma unroll
        for (int k = 0; k < 16; k++) {
            float4 a_0 = *(const float4*)&As[k][ty * 8];
            float4 a_1 = *(const float4*)&As[k][ty * 8 + 4];
            float4 b_0 = *(const float4*)&Bs[k][tx * 8];
            float4 b_1 = *(const float4*)&Bs[k][tx * 8 + 4];
            float ar[8] = {a_0.x, a_0.y, a_0.z, a_0.w, a_1.x, a_1.y, a_1.z, a_1.w};
            float br[8] = {b_0.x, b_0.y, b_0.z, b_0.w, b_1.x, b_1.y, b_1.z, b_1.w};
            #pragma unroll
            for (int i = 0; i < 8; i++)
                #pragma unroll
                for (int j = 0; j < 8; j++)
                    c[i][j] = fmaf(ar[i], br[j], c[i][j]);
        }
    }

    #pragma unroll
    for (int i = 0; i < 8; i++) {
        int gr = rowBase + ty * 8 + i;
        #pragma unroll
        for (int j = 0; j < 8; j++) {
            int gc = colBase + tx * 8 + j;
            if (gc < C) out[(size_t)gr * C + gc] = c[i][j] + __ldg(&bias[gc]);
        }
    }
}

// ---------------------------------------------------------------------------
// CE per row  (identical to R5)
__global__ __launch_bounds__(256) void k_ce(const float* __restrict__ logits,
                                            const int* __restrict__ labels) {
    int row = blockIdx.x;
    int tid = threadIdx.x;
    const float* x = logits + (size_t)row * C;
    float m = -1e30f;
    for (int j = tid; j < C; j += 256) m = fmaxf(m, x[j]);
    __shared__ float red[8];
    __shared__ float bc;
    for (int o = 16; o > 0; o >>= 1) m = fmaxf(m, __shfl_xor_sync(0xffffffffu, m, o));
    if ((tid & 31) == 0) red[tid >> 5] = m;
    __syncthreads();
    if (tid == 0) {
        float v = red[0];
        #pragma unroll
        for (int w = 1; w < 8; w++) v = fmaxf(v, red[w]);
        bc = v;
    }
    __syncthreads();
    m = bc;
    float s = 0.f;
    for (int j = tid; j < C; j += 256) s += expf(x[j] - m);
    for (int o = 16; o > 0; o >>= 1) s += __shfl_xor_sync(0xffffffffu, s, o);
    if ((tid & 31) == 0) red[tid >> 5] = s;
    __syncthreads();
    if (tid == 0) {
        float v = 0.f;
        #pragma unroll
        for (int w = 0; w < 8; w++) v += red[w];
        int lab = labels[row];
        g_ce[row] = -(x[lab] - m - logf(v));
    }
}

// ---------------------------------------------------------------------------
// SCL sim GEMM via mma.sync bf16 — SYMMETRIC version: only lower-triangular
// block tiles (2080 of 4096). Off-diagonal tiles emit the epilogue both ways
// (row side as before; column side via g-group shfl reduction + atomics).
#define SCL_SMEM (1024 + 2 * 32768)
#define NKC 16
#define NTILE 64                       // N / 128
#define NBLOCKS (NTILE * (NTILE + 1) / 2)   // 2080

__global__ __launch_bounds__(256) void k_scl_mma(const int* __restrict__ labels) {
    extern __shared__ char smem[];
    const uint32_t sb = smem_u32(smem);
    const int tid = threadIdx.x;
    const int lane = tid & 31;
    const int wid = tid >> 5;

    // map linear bid -> lower-triangular (I, J), I >= J
    const int bid = blockIdx.x;
    int I = (int)((sqrtf(8.f * (float)bid + 1.f) - 1.f) * 0.5f);
    while ((I + 1) * (I + 2) / 2 <= bid) I++;
    while (I * (I + 1) / 2 > bid) I--;
    const int J = bid - I * (I + 1) / 2;
    const int rowBase = I * 128;
    const int colBase = J * 128;
    const bool offdiag = (I != J);

    int* rowLab = (int*)smem;
    int* colLab = (int*)(smem + 512);
    if (tid < 128) rowLab[tid] = labels[rowBase + tid];
    else           colLab[tid - 128] = labels[colBase + tid - 128];

    const int ldr = tid >> 3;
    const int ldc = (tid & 7) * 16;
    const char* gb = (const char*)g_featb;

    const int mr = (wid >> 1) * 32;
    const int nc = (wid & 1) * 64;

    float acc[2][8][4];
    #pragma unroll
    for (int i = 0; i < 2; i++)
        #pragma unroll
        for (int j = 0; j < 8; j++)
            #pragma unroll
            for (int u = 0; u < 4; u++) acc[i][j][u] = 0.f;

    uint32_t sA[2], sB[2];
    #pragma unroll
    for (int s = 0; s < 2; s++) { sA[s] = sb + 1024 + s * 32768; sB[s] = sA[s] + 16384; }

    {
        #pragma unroll
        for (int rr = 0; rr < 4; rr++) {
            int r = ldr + rr * 32;
            uint32_t sw = SWZ((uint32_t)(r * 128 + ldc));
            cp16(sA[0] + sw, gb + (size_t)(rowBase + r) * 2048 + ldc);
            cp16(sB[0] + sw, gb + (size_t)(colBase + r) * 2048 + ldc);
        }
        CP_COMMIT();
    }

    for (int kc = 0; kc < NKC; kc++) {
        if (kc + 1 < NKC) {
            const int s = (kc + 1) & 1;
            const size_t go = (size_t)(kc + 1) * 128 + ldc;
            #pragma unroll
            for (int rr = 0; rr < 4; rr++) {
                int r = ldr + rr * 32;
                uint32_t sw = SWZ((uint32_t)(r * 128 + ldc));
                cp16(sA[s] + sw, gb + (size_t)(rowBase + r) * 2048 + go);
                cp16(sB[s] + sw, gb + (size_t)(colBase + r) * 2048 + go);
            }
            CP_COMMIT();
            CP_WAIT1();
        } else {
            CP_WAIT0();
        }
        __syncthreads();

        const uint32_t bufA = sA[kc & 1];
        const uint32_t bufB = sB[kc & 1];
        const int klane = (lane >> 4) << 4;
        #pragma unroll
        for (int ks = 0; ks < 4; ks++) {
            const int kb = ks * 32 + klane;
            uint32_t af[2][4];
            #pragma unroll
            for (int i = 0; i < 2; i++) {
                int r = mr + i * 16 + (lane & 15);
                ldm_x4(af[i], bufA + SWZ((uint32_t)(r * 128 + kb)));
            }
            #pragma unroll
            for (int j = 0; j < 4; j++) {
                uint32_t bf[4];
                int nr = nc + j * 16 + (lane & 15);
                ldm_x4(bf, bufB + SWZ((uint32_t)(nr * 128 + kb)));
                #pragma unroll
                for (int i = 0; i < 2; i++) {
                    mma_bf16(acc[i][j * 2 + 0], af[i], bf[0], bf[1]);
                    mma_bf16(acc[i][j * 2 + 1], af[i], bf[2], bf[3]);
                }
            }
        }
        __syncthreads();
    }

    // ---- fused epilogue: row side always; column side for off-diagonal ----
    const int g = lane >> 2, t = lane & 3;
    const float invt = 1.0f / 0.3f;

    // the 4 rows this lane covers: (i=0: r0, r0+8), (i=1: r0+16, r0+24)
    int rIdx[4], rGlb[4], rLb[4];
    #pragma unroll
    for (int i = 0; i < 2; i++) {
        rIdx[i * 2 + 0] = mr + i * 16 + g;
        rIdx[i * 2 + 1] = mr + i * 16 + g + 8;
    }
    #pragma unroll
    for (int q = 0; q < 4; q++) { rGlb[q] = rowBase + rIdx[q]; rLb[q] = rowLab[rIdx[q]]; }

    float rse[4] = {0.f, 0.f, 0.f, 0.f};
    float rps[4] = {0.f, 0.f, 0.f, 0.f};

    #pragma unroll
    for (int j = 0; j < 8; j++) {
        float cse[2] = {0.f, 0.f};
        float cps[2] = {0.f, 0.f};
        #pragma unroll
        for (int i = 0; i < 2; i++) {
            #pragma unroll
            for (int u = 0; u < 2; u++) {
                const int col = nc + j * 8 + t * 2 + u;
                const int gc = colBase + col;
                const int cl = colLab[col];
                const float s0 = acc[i][j][u] * invt;        // row rIdx[i*2]
                const float s1 = acc[i][j][2 + u] * invt;    // row rIdx[i*2+1]
                const float e0 = __expf(s0);
                const float e1 = __expf(s1);
                // row side (diagonal exclusion only matters when I==J)
                if (gc != rGlb[i * 2 + 0]) { rse[i * 2 + 0] += e0; if (cl == rLb[i * 2 + 0]) rps[i * 2 + 0] += s0; }
                if (gc != rGlb[i * 2 + 1]) { rse[i * 2 + 1] += e1; if (cl == rLb[i * 2 + 1]) rps[i * 2 + 1] += s1; }
                // column side (sim symmetric; off-diag tiles never hit r==c)
                if (offdiag) {
                    cse[u] += e0 + e1;
                    if (rLb[i * 2 + 0] == cl) cps[u] += s0;
                    if (rLb[i * 2 + 1] == cl) cps[u] += s1;
                }
            }
        }
        if (offdiag) {
            // reduce over the 8 g-groups (lanes sharing t): xor 4, 8, 16
            #pragma unroll
            for (int o = 4; o <= 16; o <<= 1) {
                cse[0] += __shfl_xor_sync(0xffffffffu, cse[0], o);
                cps[0] += __shfl_xor_sync(0xffffffffu, cps[0], o);
                cse[1] += __shfl_xor_sync(0xffffffffu, cse[1], o);
                cps[1] += __shfl_xor_sync(0xffffffffu, cps[1], o);
            }
            if (g == 0) {
                const int colb = colBase + nc + j * 8 + t * 2;
                atomicAdd(&g_sumexp[colb + 0], cse[0]);
                atomicAdd(&g_possum[colb + 0], cps[0]);
                atomicAdd(&g_sumexp[colb + 1], cse[1]);
                atomicAdd(&g_possum[colb + 1], cps[1]);
            }
        }
    }

    // row-side reduction across the 4 t-lanes sharing each row
    #pragma unroll
    for (int q = 0; q < 4; q++) {
        #pragma unroll
        for (int o = 1; o <= 2; o <<= 1) {
            rse[q] += __shfl_xor_sync(0xffffffffu, rse[q], o);
            rps[q] += __shfl_xor_sync(0xffffffffu, rps[q], o);
        }
    }
    if (t == 0) {
        #pragma unroll
        for (int q = 0; q < 4; q++) {
            atomicAdd(&g_sumexp[rGlb[q]], rse[q]);
            atomicAdd(&g_possum[rGlb[q]], rps[q]);
        }
    }
}

// ---------------------------------------------------------------------------
__global__ __launch_bounds__(256) void k_final(const int* __restrict__ labels,
                                               float* __restrict__ out_loss) {
    int tid = threadIdx.x;
    float ce = 0.f, scl = 0.f;
    int nv = 0;
    for (int i = tid; i < N; i += 256) {
        ce += g_ce[i];
        int cnt = g_hist[labels[i]] - 1;
        if (cnt > 0) {
            float lse = logf(g_sumexp[i]);
            scl += lse - g_possum[i] / (float)cnt;
            nv++;
        }
    }
    __shared__ float sc[256], ss[256];
    __shared__ int sn[256];
    sc[tid] = ce; ss[tid] = scl; sn[tid] = nv;
    __syncthreads();
    for (int o = 128; o > 0; o >>= 1) {
        if (tid < o) { sc[tid] += sc[tid + o]; ss[tid] += ss[tid + o]; sn[tid] += sn[tid + o]; }
        __syncthreads();
    }
    if (tid == 0) {
        float cem = sc[0] / (float)N;
        float sclm = (sn[0] > 0) ? (ss[0] / (float)sn[0]) : 0.f;
        *out_loss = 0.9f * cem + 0.1f * sclm;
    }
}

// ---------------------------------------------------------------------------
extern "C" void kernel_launch(void* const* d_in, const int* in_sizes, int n_in,
                              void* d_out, int out_size) {
    const float* feat   = (const float*)d_in[0];
    const int*   labels = (const int*)d_in[1];
    const float* W      = (const float*)d_in[2];
    const float* b      = (const float*)d_in[3];
    float* out = (float*)d_out;

    static int smem_set = 0;
    if (!smem_set) {
        cudaFuncSetAttribute(k_scl_mma, cudaFuncAttributeMaxDynamicSharedMemorySize, SCL_SMEM);
        smem_set = 1;
    }

    k_init<<<(N + 255) / 256, 256>>>();
    k_norm_hist<<<N, 256>>>(feat, labels);
    k_logits<<<dim3((C + 127) / 128, N / 128), 256>>>(feat, W, b, out);
    k_ce<<<N, 256>>>(out, labels);
    k_scl_mma<<<NBLOCKS, 256, SCL_SMEM>>>(labels);
    k_final<<<1, 256>>>(labels, out + (size_t)out_size - 1);
}